// round 3
// baseline (speedup 1.0000x reference)
#include <cuda_runtime.h>
#include <cuda_bf16.h>
#include <cstdint>

// Problem constants
#define N_ROWS     131072
#define D_IN       512
#define D_H        1024
#define D_OUT      128
#define NUM_GROUPS 1024
#define LN_EPS     1e-5f

// ---------------------------------------------------------------------------
// Device scratch (no cudaMalloc allowed)
// ---------------------------------------------------------------------------
__device__ float g_h1[(size_t)N_ROWS * D_H];     // layer1 act (post-LN, tf32-rounded)
__device__ float g_h2[(size_t)N_ROWS * D_H];     // layer2 act (post-LN, tf32-rounded)
__device__ float g_xc[(size_t)N_ROWS * D_IN];    // X rounded to tf32
__device__ float g_w1[(size_t)D_IN * D_H];       // W1 rounded to tf32
__device__ float g_w2[(size_t)D_H * D_H];        // W2 rounded to tf32
__device__ float g_w3[(size_t)D_H * D_OUT];      // W3 rounded to tf32
__device__ float g_counts[NUM_GROUPS];

// ---------------------------------------------------------------------------
// Helpers
// ---------------------------------------------------------------------------
__device__ __forceinline__ float tf32_rna(float x) {
    uint32_t u;
    asm("cvt.rna.tf32.f32 %0, %1;" : "=r"(u) : "f"(x));
    return __uint_as_float(u);
}

__device__ __forceinline__ void cp_async16(uint32_t dst_smem, const void* src) {
    asm volatile("cp.async.cg.shared.global [%0], [%1], 16;\n"
                 :: "r"(dst_smem), "l"(src));
}
__device__ __forceinline__ void cp_commit() {
    asm volatile("cp.async.commit_group;\n" ::);
}
template <int N>
__device__ __forceinline__ void cp_wait() {
    asm volatile("cp.async.wait_group %0;\n" :: "n"(N));
}

__device__ __forceinline__ void mma_tf32(float* c, const uint32_t* a, const uint32_t* b) {
    asm volatile(
        "mma.sync.aligned.m16n8k8.row.col.f32.tf32.tf32.f32 "
        "{%0,%1,%2,%3}, {%4,%5,%6,%7}, {%8,%9}, {%0,%1,%2,%3};\n"
        : "+f"(c[0]), "+f"(c[1]), "+f"(c[2]), "+f"(c[3])
        : "r"(a[0]), "r"(a[1]), "r"(a[2]), "r"(a[3]), "r"(b[0]), "r"(b[1]));
}

// ---------------------------------------------------------------------------
// TF32 tensor-core GEMM: C[M,Ncols] = A[M,K] @ B[K,Ncols] + bias, fused epi:
//   EPI == 0 : C = relu(.), stored (ldc == ldb)
//   EPI == 1 : atomicAdd into out[batch[row]*D_OUT + col]  (segment sum)
// BM=256, BN=128, BK=32, 256 threads, 8 warps (4x2), warp tile 64x64,
// per-warp 4x8 m16n8k8 fragments, 3-stage cp.async pipeline.
// Inputs A,B must be pre-rounded to tf32 (rna) so MMA truncation is exact.
// Requires M%256==0, Ncols%128==0, K%32==0.
// smem per stage: A [256][36] + B [32][136] floats; 3 stages = 162816 B.
// ---------------------------------------------------------------------------
#define A_STG 9216    // 256*36 floats
#define B_STG 4352    // 32*136 floats
#define STG   (A_STG + B_STG)
#define GEMM_SMEM (3 * STG * 4)

template <int EPI>
__global__ void __launch_bounds__(256, 1)
tf32_gemm(const float* __restrict__ A,
          const float* __restrict__ B,
          const float* __restrict__ bias,
          float* __restrict__ C,
          int K, int lda, int ldb,
          const int* __restrict__ batch,
          float* __restrict__ out)
{
    extern __shared__ float smem[];
    const uint32_t sb = (uint32_t)__cvta_generic_to_shared(smem);

    const int tid = threadIdx.x;
    const int m0 = blockIdx.y * 256;
    const int n0 = blockIdx.x * 128;

    const int wid  = tid >> 5, lane = tid & 31;
    const int wm   = wid >> 1;          // warp row (0..3) -> 64 rows each
    const int wn   = wid & 1;           // warp col (0..1) -> 64 cols each
    const int g    = lane >> 2;         // 0..7
    const int t    = lane & 3;          // 0..3

    float acc[4][8][4];
    #pragma unroll
    for (int i = 0; i < 4; i++)
        #pragma unroll
        for (int j = 0; j < 8; j++)
            #pragma unroll
            for (int r = 0; r < 4; r++) acc[i][j][r] = 0.f;

    const int iters = K >> 5;

    // ---- tile loader (cp.async), stage s ----
    auto load_tiles = [&](int k0, int s) {
        const uint32_t base = (uint32_t)(s * STG);
        #pragma unroll
        for (int c = 0; c < 8; c++) {
            int chunk = tid + c * 256;            // 0..2047
            int row = chunk >> 3, kc = (chunk & 7) * 4;
            cp_async16(sb + (base + row * 36 + kc) * 4,
                       A + (size_t)(m0 + row) * lda + k0 + kc);
        }
        #pragma unroll
        for (int c = 0; c < 4; c++) {
            int chunk = tid + c * 256;            // 0..1023
            int kr = chunk >> 5, nc = (chunk & 31) * 4;
            cp_async16(sb + (base + A_STG + kr * 136 + nc) * 4,
                       B + (size_t)(k0 + kr) * ldb + n0 + nc);
        }
        cp_commit();
    };

    load_tiles(0, 0);
    load_tiles(32, 1);

    for (int it = 0; it < iters; it++) {
        if (it + 2 < iters) {
            load_tiles((it + 2) * 32, (it + 2) % 3);
            cp_wait<2>();
        } else if (it + 1 < iters) {
            cp_wait<1>();
        } else {
            cp_wait<0>();
        }
        __syncthreads();

        const float* As = smem + (it % 3) * STG;
        const float* Bs = As + A_STG;

        #pragma unroll
        for (int ko = 0; ko < 32; ko += 8) {
            uint32_t a[4][4], b[8][2];
            #pragma unroll
            for (int i = 0; i < 4; i++) {
                const uint32_t* p =
                    (const uint32_t*)(As + (wm * 64 + i * 16 + g) * 36 + ko + t);
                a[i][0] = p[0];
                a[i][1] = p[8 * 36];
                a[i][2] = p[4];
                a[i][3] = p[8 * 36 + 4];
            }
            #pragma unroll
            for (int j = 0; j < 8; j++) {
                const uint32_t* p =
                    (const uint32_t*)(Bs + (ko + t) * 136 + wn * 64 + j * 8 + g);
                b[j][0] = p[0];
                b[j][1] = p[4 * 136];
            }
            #pragma unroll
            for (int i = 0; i < 4; i++)
                #pragma unroll
                for (int j = 0; j < 8; j++)
                    mma_tf32(acc[i][j], a[i], b[j]);
        }
        __syncthreads();
    }

    // bias values this thread touches: cols n0 + wn*64 + j*8 + 2t, +1
    float bv[8][2];
    #pragma unroll
    for (int j = 0; j < 8; j++) {
        int col = n0 + wn * 64 + j * 8 + 2 * t;
        bv[j][0] = bias[col];
        bv[j][1] = bias[col + 1];
    }

    if (EPI == 0) {
        #pragma unroll
        for (int i = 0; i < 4; i++) {
            int r0 = m0 + wm * 64 + i * 16 + g;
            #pragma unroll
            for (int j = 0; j < 8; j++) {
                int col = n0 + wn * 64 + j * 8 + 2 * t;
                float2 v0, v1;
                v0.x = fmaxf(acc[i][j][0] + bv[j][0], 0.f);
                v0.y = fmaxf(acc[i][j][1] + bv[j][1], 0.f);
                v1.x = fmaxf(acc[i][j][2] + bv[j][0], 0.f);
                v1.y = fmaxf(acc[i][j][3] + bv[j][1], 0.f);
                *(float2*)(C + (size_t)r0 * ldb + col)       = v0;
                *(float2*)(C + (size_t)(r0 + 8) * ldb + col) = v1;
            }
        }
    } else {
        #pragma unroll
        for (int i = 0; i < 4; i++) {
            int r0 = m0 + wm * 64 + i * 16 + g;
            int g0 = batch[r0], g1 = batch[r0 + 8];
            float* o0 = out + (size_t)g0 * D_OUT;
            float* o1 = out + (size_t)g1 * D_OUT;
            #pragma unroll
            for (int j = 0; j < 8; j++) {
                int col = wn * 64 + j * 8 + 2 * t;   // n0 == 0 for layer 3
                atomicAdd(o0 + col,     acc[i][j][0] + bv[j][0]);
                atomicAdd(o0 + col + 1, acc[i][j][1] + bv[j][1]);
                atomicAdd(o1 + col,     acc[i][j][2] + bv[j][0]);
                atomicAdd(o1 + col + 1, acc[i][j][3] + bv[j][1]);
            }
        }
    }
}

// ---------------------------------------------------------------------------
// In-place row LayerNorm over D_H=1024; output rounded to tf32 (rna).
// ---------------------------------------------------------------------------
__global__ void __launch_bounds__(256)
ln_kernel(float* __restrict__ X,
          const float* __restrict__ gamma,
          const float* __restrict__ beta)
{
    const int row = blockIdx.x;
    const int tid = threadIdx.x;
    float* x = X + (size_t)row * D_H;

    float4 v = *(const float4*)(x + tid * 4);
    float s  = v.x + v.y + v.z + v.w;
    float sq = v.x * v.x + v.y * v.y + v.z * v.z + v.w * v.w;

    #pragma unroll
    for (int o = 16; o > 0; o >>= 1) {
        s  += __shfl_xor_sync(0xffffffffu, s, o);
        sq += __shfl_xor_sync(0xffffffffu, sq, o);
    }
    __shared__ float2 red[8];
    const int w = tid >> 5, l = tid & 31;
    if (l == 0) red[w] = make_float2(s, sq);
    __syncthreads();
    if (w == 0) {
        float2 p = (l < 8) ? red[l] : make_float2(0.f, 0.f);
        s = p.x; sq = p.y;
        #pragma unroll
        for (int o = 4; o > 0; o >>= 1) {
            s  += __shfl_xor_sync(0xffffffffu, s, o);
            sq += __shfl_xor_sync(0xffffffffu, sq, o);
        }
        if (l == 0) red[0] = make_float2(s, sq);
    }
    __syncthreads();

    const float mean = red[0].x * (1.0f / D_H);
    const float var  = red[0].y * (1.0f / D_H) - mean * mean;
    const float inv  = rsqrtf(var + LN_EPS);

    float4 gg = *(const float4*)(gamma + tid * 4);
    float4 bb = *(const float4*)(beta  + tid * 4);
    float4 o;
    o.x = tf32_rna((v.x - mean) * inv * gg.x + bb.x);
    o.y = tf32_rna((v.y - mean) * inv * gg.y + bb.y);
    o.z = tf32_rna((v.z - mean) * inv * gg.z + bb.z);
    o.w = tf32_rna((v.w - mean) * inv * gg.w + bb.w);
    *(float4*)(x + tid * 4) = o;
}

// ---------------------------------------------------------------------------
// Small helper kernels
// ---------------------------------------------------------------------------
__global__ void cvt_kernel(const float* __restrict__ src,
                           float* __restrict__ dst, int n4)
{
    int i = blockIdx.x * blockDim.x + threadIdx.x;
    if (i < n4) {
        float4 v = ((const float4*)src)[i];
        v.x = tf32_rna(v.x); v.y = tf32_rna(v.y);
        v.z = tf32_rna(v.z); v.w = tf32_rna(v.w);
        ((float4*)dst)[i] = v;
    }
}

__global__ void zero_kernel(float* __restrict__ out)
{
    int i = blockIdx.x * blockDim.x + threadIdx.x;
    if (i < NUM_GROUPS * D_OUT) out[i] = 0.f;
    if (i < NUM_GROUPS) g_counts[i] = 0.f;
}

__global__ void count_kernel(const int* __restrict__ batch)
{
    int i = blockIdx.x * blockDim.x + threadIdx.x;
    if (i < N_ROWS) atomicAdd(&g_counts[batch[i]], 1.0f);
}

__global__ void finalize_kernel(float* __restrict__ out)
{
    int i = blockIdx.x * blockDim.x + threadIdx.x;
    if (i < NUM_GROUPS * D_OUT) out[i] = out[i] / g_counts[i / D_OUT];
}

// ---------------------------------------------------------------------------
// kernel_launch
// Inputs: X, W1, b1, g1, be1, W2, b2, g2, be2, W3, b3, all_batch
// Launch order puts the two big GEMMs at positions 4 and 6 so the ncu
// single-kernel capture lands on one of them.
// ---------------------------------------------------------------------------
extern "C" void kernel_launch(void* const* d_in, const int* in_sizes, int n_in,
                              void* d_out, int out_size)
{
    const float* X   = (const float*)d_in[0];
    const float* W1  = (const float*)d_in[1];
    const float* b1  = (const float*)d_in[2];
    const float* g1  = (const float*)d_in[3];
    const float* be1 = (const float*)d_in[4];
    const float* W2  = (const float*)d_in[5];
    const float* b2  = (const float*)d_in[6];
    const float* g2  = (const float*)d_in[7];
    const float* be2 = (const float*)d_in[8];
    const float* W3  = (const float*)d_in[9];
    const float* b3  = (const float*)d_in[10];
    const int*   batch = (const int*)d_in[11];
    float* outp = (float*)d_out;

    float *h1, *h2, *xc, *w1c, *w2c, *w3c;
    cudaGetSymbolAddress((void**)&h1,  g_h1);
    cudaGetSymbolAddress((void**)&h2,  g_h2);
    cudaGetSymbolAddress((void**)&xc,  g_xc);
    cudaGetSymbolAddress((void**)&w1c, g_w1);
    cudaGetSymbolAddress((void**)&w2c, g_w2);
    cudaGetSymbolAddress((void**)&w3c, g_w3);

    cudaFuncSetAttribute(tf32_gemm<0>,
        cudaFuncAttributeMaxDynamicSharedMemorySize, GEMM_SMEM);
    cudaFuncSetAttribute(tf32_gemm<1>,
        cudaFuncAttributeMaxDynamicSharedMemorySize, GEMM_SMEM);

    // 1: W2 rounding (needed before gemm2)
    cvt_kernel<<<(D_H * D_H / 4 + 255) / 256, 256>>>(W2, w2c, D_H * D_H / 4);
    // 2: W1 rounding
    cvt_kernel<<<(D_IN * D_H / 4 + 255) / 256, 256>>>(W1, w1c, D_IN * D_H / 4);
    // 3: X rounding
    cvt_kernel<<<(N_ROWS * D_IN / 4 + 255) / 256, 256>>>(X, xc, N_ROWS * D_IN / 4);

    // 4: layer 1 GEMM  h1 = relu(Xc @ W1c + b1)
    tf32_gemm<0><<<dim3(D_H / 128, N_ROWS / 256), 256, GEMM_SMEM>>>(
        xc, w1c, b1, h1, D_IN, D_IN, D_H, nullptr, nullptr);
    // 5: LN1 in-place
    ln_kernel<<<N_ROWS, 256>>>(h1, g1, be1);

    // 6: layer 2 GEMM  h2 = relu(h1 @ W2c + b2)
    tf32_gemm<0><<<dim3(D_H / 128, N_ROWS / 256), 256, GEMM_SMEM>>>(
        h1, w2c, b2, h2, D_H, D_H, D_H, nullptr, nullptr);
    // 7: LN2 in-place
    ln_kernel<<<N_ROWS, 256>>>(h2, g2, be2);

    // 8: W3 rounding; 9: zero out+counts; 10: counts
    cvt_kernel<<<(D_H * D_OUT / 4 + 255) / 256, 256>>>(W3, w3c, D_H * D_OUT / 4);
    zero_kernel<<<(NUM_GROUPS * D_OUT + 255) / 256, 256>>>(outp);
    count_kernel<<<(N_ROWS + 255) / 256, 256>>>(batch);

    // 11: layer 3 GEMM + segment-sum atomics
    tf32_gemm<1><<<dim3(D_OUT / 128, N_ROWS / 256), 256, GEMM_SMEM>>>(
        h2, w3c, b3, nullptr, D_H, D_H, D_OUT, batch, outp);

    // 12: mean = sum / count
    finalize_kernel<<<(NUM_GROUPS * D_OUT + 255) / 256, 256>>>(outp);
}

// round 7
// speedup vs baseline: 1.6701x; 1.6701x over previous
#include <cuda_runtime.h>
#include <cuda_fp16.h>
#include <cstdint>

// ---------------------------------------------------------------------------
// Problem constants
// ---------------------------------------------------------------------------
#define N_ROWS     131072
#define D_IN       512
#define D_H        1024
#define D_OUT      128
#define NUM_GROUPS 1024
#define LN_EPS     1e-5f

// ---------------------------------------------------------------------------
// Device scratch (no cudaMalloc allowed)
// ---------------------------------------------------------------------------
__device__ __half g_h1[(size_t)N_ROWS * D_H];   // layer1 act (post-LN, fp16)
__device__ __half g_h2[(size_t)N_ROWS * D_H];   // layer2 act (post-LN, fp16)
__device__ __half g_xh[(size_t)N_ROWS * D_IN];  // X in fp16
__device__ __half g_w1t[(size_t)D_H * D_IN];    // W1^T [N][K] fp16
__device__ __half g_w2t[(size_t)D_H * D_H];     // W2^T [N][K] fp16
__device__ __half g_w3t[(size_t)D_OUT * D_H];   // W3^T [N][K] fp16
__device__ float  g_counts[NUM_GROUPS];

// ---------------------------------------------------------------------------
// Helpers
// ---------------------------------------------------------------------------
__device__ __forceinline__ uint32_t smem_u32(const void* p) {
    uint32_t a;
    asm("{ .reg .u64 t; cvta.to.shared.u64 t, %1; cvt.u32.u64 %0, t; }"
        : "=r"(a) : "l"(p));
    return a;
}
__device__ __forceinline__ void cp_async16(uint32_t dst, const void* src) {
    asm volatile("cp.async.cg.shared.global [%0], [%1], 16;\n"
                 :: "r"(dst), "l"(src));
}
__device__ __forceinline__ void cp_commit() {
    asm volatile("cp.async.commit_group;\n" ::);
}
template <int N>
__device__ __forceinline__ void cp_wait() {
    asm volatile("cp.async.wait_group %0;\n" :: "n"(N));
}

__device__ __forceinline__ void mma_f16(float* c, const uint32_t* a, const uint32_t* b) {
    asm volatile(
        "mma.sync.aligned.m16n8k16.row.col.f32.f16.f16.f32 "
        "{%0,%1,%2,%3}, {%4,%5,%6,%7}, {%8,%9}, {%0,%1,%2,%3};\n"
        : "+f"(c[0]), "+f"(c[1]), "+f"(c[2]), "+f"(c[3])
        : "r"(a[0]), "r"(a[1]), "r"(a[2]), "r"(a[3]), "r"(b[0]), "r"(b[1]));
}

// ---------------------------------------------------------------------------
// FP16 tensor-core GEMM: C[M,Nc] = A[M,K] @ Bt[Nc,K]^T + bias
//   EPI == 0 : C(half) = relu(.), row-major ldc
//   EPI == 1 : atomicAdd into out[batch[row]*D_OUT + col] (fp32 segment sum)
// BM=256, BN=128, BK=64, 512 threads, 16 warps (4x4), warp tile 64x32,
// per-warp 4x4 m16n8k16 fragments, 3-stage cp.async pipeline.
// SMEM rows padded to 72 halves (144 B) -> conflict-free LDS.32 fragments.
// Requires M%256==0, Nc==128, K%64==0.
// ---------------------------------------------------------------------------
#define A_HALVES 18432                 // 256*72
#define A_BYTES2 36864
#define STG_B    55296                 // A_BYTES2 + 128*72*2
#define GEMM_SMEM (3 * STG_B)          // 165888

template <int EPI>
__global__ void __launch_bounds__(512, 1)
h_gemm(const __half* __restrict__ A,
       const __half* __restrict__ Bt,
       const float* __restrict__ bias,
       __half* __restrict__ C,
       int K, int lda, int ldc,
       const int* __restrict__ batch,
       float* __restrict__ out)
{
    extern __shared__ char smem[];
    const uint32_t sb = smem_u32(smem);

    const int tid = threadIdx.x;
    const int wid = tid >> 5, lane = tid & 31;
    const int wm = wid >> 2;            // 0..3 -> 64 rows
    const int wn = wid & 3;             // 0..3 -> 32 cols
    const int g  = lane >> 2;           // 0..7
    const int t  = lane & 3;            // 0..3

    const int m0 = blockIdx.y * 256;
    const int n0 = blockIdx.x * 128;

    float acc[4][4][4];
    #pragma unroll
    for (int i = 0; i < 4; i++)
        #pragma unroll
        for (int j = 0; j < 4; j++)
            #pragma unroll
            for (int r = 0; r < 4; r++) acc[i][j][r] = 0.f;

    const __half* Arow = A  + (size_t)m0 * lda;
    const __half* Brow = Bt + (size_t)n0 * K;

    auto load_stage = [&](int k0, int s) {   // k0 in halves
        const uint32_t base = sb + s * STG_B;
        #pragma unroll
        for (int c = 0; c < 4; c++) {        // A: 2048 16B chunks
            int chunk = tid + c * 512;
            int row = chunk >> 3, k16 = chunk & 7;
            cp_async16(base + row * 144 + k16 * 16,
                       Arow + (size_t)row * lda + k0 + k16 * 8);
        }
        #pragma unroll
        for (int c = 0; c < 2; c++) {        // B: 1024 16B chunks
            int chunk = tid + c * 512;
            int row = chunk >> 3, k16 = chunk & 7;
            cp_async16(base + A_BYTES2 + row * 144 + k16 * 16,
                       Brow + (size_t)row * K + k0 + k16 * 8);
        }
        cp_commit();
    };

    const int iters = K >> 6;
    load_stage(0, 0);
    load_stage(64, 1);

    for (int it = 0; it < iters; it++) {
        if (it + 2 < iters) {
            load_stage((it + 2) * 64, (it + 2) % 3);
            cp_wait<2>();
        } else if (it + 1 < iters) {
            cp_wait<1>();
        } else {
            cp_wait<0>();
        }
        __syncthreads();

        const __half* As = (const __half*)(smem + (it % 3) * STG_B);
        const __half* Bs = As + A_HALVES;

        #pragma unroll
        for (int ko = 0; ko < 4; ko++) {     // 4 x k16 per BK=64
            uint32_t a[4][4], b[4][2];
            #pragma unroll
            for (int i = 0; i < 4; i++) {
                const uint32_t* p = (const uint32_t*)
                    (As + (wm * 64 + i * 16 + g) * 72 + ko * 16 + 2 * t);
                a[i][0] = p[0];          // (g,      k 2t..2t+1)
                a[i][1] = p[8 * 36];     // (g+8,    k 2t..2t+1)
                a[i][2] = p[4];          // (g,      k 8+2t..)
                a[i][3] = p[8 * 36 + 4]; // (g+8,    k 8+2t..)
            }
            #pragma unroll
            for (int j = 0; j < 4; j++) {
                const uint32_t* q = (const uint32_t*)
                    (Bs + (wn * 32 + j * 8 + g) * 72 + ko * 16 + 2 * t);
                b[j][0] = q[0];
                b[j][1] = q[4];
            }
            #pragma unroll
            for (int i = 0; i < 4; i++)
                #pragma unroll
                for (int j = 0; j < 4; j++)
                    mma_f16(acc[i][j], a[i], b[j]);
        }
        __syncthreads();
    }

    // bias values: cols n0 + wn*32 + j*8 + 2t, +1
    float bv[4][2];
    #pragma unroll
    for (int j = 0; j < 4; j++) {
        int col = n0 + wn * 32 + j * 8 + 2 * t;
        bv[j][0] = bias[col];
        bv[j][1] = bias[col + 1];
    }

    if (EPI == 0) {
        #pragma unroll
        for (int i = 0; i < 4; i++) {
            int r0 = m0 + wm * 64 + i * 16 + g;
            __half* c0 = C + (size_t)r0 * ldc + n0;
            __half* c1 = C + (size_t)(r0 + 8) * ldc + n0;
            #pragma unroll
            for (int j = 0; j < 4; j++) {
                int col = wn * 32 + j * 8 + 2 * t;
                *(__half2*)(c0 + col) = __floats2half2_rn(
                    fmaxf(acc[i][j][0] + bv[j][0], 0.f),
                    fmaxf(acc[i][j][1] + bv[j][1], 0.f));
                *(__half2*)(c1 + col) = __floats2half2_rn(
                    fmaxf(acc[i][j][2] + bv[j][0], 0.f),
                    fmaxf(acc[i][j][3] + bv[j][1], 0.f));
            }
        }
    } else {
        #pragma unroll
        for (int i = 0; i < 4; i++) {
            int r0 = m0 + wm * 64 + i * 16 + g;
            int q0 = batch[r0], q1 = batch[r0 + 8];
            float* o0 = out + (size_t)q0 * D_OUT;
            float* o1 = out + (size_t)q1 * D_OUT;
            #pragma unroll
            for (int j = 0; j < 4; j++) {
                int col = wn * 32 + j * 8 + 2 * t;   // n0 == 0 here
                atomicAdd(o0 + col,     acc[i][j][0] + bv[j][0]);
                atomicAdd(o0 + col + 1, acc[i][j][1] + bv[j][1]);
                atomicAdd(o1 + col,     acc[i][j][2] + bv[j][0]);
                atomicAdd(o1 + col + 1, acc[i][j][3] + bv[j][1]);
            }
        }
    }
}

// ---------------------------------------------------------------------------
// In-place row LayerNorm over D_H=1024 fp16; stats in fp32.
// ---------------------------------------------------------------------------
__global__ void __launch_bounds__(256)
ln_kernel(__half* __restrict__ X,
          const float* __restrict__ gamma,
          const float* __restrict__ beta)
{
    const int row = blockIdx.x;
    const int tid = threadIdx.x;
    __half* x = X + (size_t)row * D_H;

    uint2 u = *(const uint2*)(x + tid * 4);
    float2 p0 = __half22float2(*(__half2*)&u.x);
    float2 p1 = __half22float2(*(__half2*)&u.y);
    float s  = p0.x + p0.y + p1.x + p1.y;
    float sq = p0.x * p0.x + p0.y * p0.y + p1.x * p1.x + p1.y * p1.y;

    #pragma unroll
    for (int o = 16; o > 0; o >>= 1) {
        s  += __shfl_xor_sync(0xffffffffu, s, o);
        sq += __shfl_xor_sync(0xffffffffu, sq, o);
    }
    __shared__ float2 red[8];
    const int w = tid >> 5, l = tid & 31;
    if (l == 0) red[w] = make_float2(s, sq);
    __syncthreads();
    if (w == 0) {
        float2 p = (l < 8) ? red[l] : make_float2(0.f, 0.f);
        s = p.x; sq = p.y;
        #pragma unroll
        for (int o = 4; o > 0; o >>= 1) {
            s  += __shfl_xor_sync(0xffffffffu, s, o);
            sq += __shfl_xor_sync(0xffffffffu, sq, o);
        }
        if (l == 0) red[0] = make_float2(s, sq);
    }
    __syncthreads();

    const float mean = red[0].x * (1.0f / D_H);
    const float var  = red[0].y * (1.0f / D_H) - mean * mean;
    const float inv  = rsqrtf(var + LN_EPS);

    float4 gg = *(const float4*)(gamma + tid * 4);
    float4 bb = *(const float4*)(beta  + tid * 4);
    uint2 o;
    *(__half2*)&o.x = __floats2half2_rn((p0.x - mean) * inv * gg.x + bb.x,
                                        (p0.y - mean) * inv * gg.y + bb.y);
    *(__half2*)&o.y = __floats2half2_rn((p1.x - mean) * inv * gg.z + bb.z,
                                        (p1.y - mean) * inv * gg.w + bb.w);
    *(uint2*)(x + tid * 4) = o;
}

// ---------------------------------------------------------------------------
// Small helper kernels
// ---------------------------------------------------------------------------
__global__ void cvt_x_kernel(const float* __restrict__ src,
                             __half* __restrict__ dst, int n4)
{
    int i = blockIdx.x * blockDim.x + threadIdx.x;
    if (i < n4) {
        float4 v = ((const float4*)src)[i];
        uint2 o;
        *(__half2*)&o.x = __floats2half2_rn(v.x, v.y);
        *(__half2*)&o.y = __floats2half2_rn(v.z, v.w);
        ((uint2*)dst)[i] = o;
    }
}

// dst[n*K + k] = fp16(src[k*N + n]); grid (N/32, K/32), 256 threads
__global__ void wtrans_kernel(const float* __restrict__ src,
                              __half* __restrict__ dst, int K, int N)
{
    __shared__ float t[32][33];
    const int n0 = blockIdx.x * 32, k0 = blockIdx.y * 32;
    const int tx = threadIdx.x & 31, ty = threadIdx.x >> 5;
    #pragma unroll
    for (int r = ty; r < 32; r += 8)
        t[r][tx] = src[(size_t)(k0 + r) * N + n0 + tx];
    __syncthreads();
    #pragma unroll
    for (int r = ty; r < 32; r += 8)
        dst[(size_t)(n0 + r) * K + k0 + tx] = __float2half_rn(t[tx][r]);
}

__global__ void zero_kernel(float* __restrict__ out)
{
    int i = blockIdx.x * blockDim.x + threadIdx.x;
    if (i < NUM_GROUPS * D_OUT) out[i] = 0.f;
    if (i < NUM_GROUPS) g_counts[i] = 0.f;
}

__global__ void count_kernel(const int* __restrict__ batch)
{
    int i = blockIdx.x * blockDim.x + threadIdx.x;
    if (i < N_ROWS) atomicAdd(&g_counts[batch[i]], 1.0f);
}

__global__ void finalize_kernel(float* __restrict__ out)
{
    int i = blockIdx.x * blockDim.x + threadIdx.x;
    if (i < NUM_GROUPS * D_OUT) out[i] = out[i] / g_counts[i / D_OUT];
}

// ---------------------------------------------------------------------------
// kernel_launch
// Inputs: X, W1, b1, g1, be1, W2, b2, g2, be2, W3, b3, all_batch
// Layer-2 GEMM is the 6th launch (ncu -s 5 -c 1 captures it).
// ---------------------------------------------------------------------------
extern "C" void kernel_launch(void* const* d_in, const int* in_sizes, int n_in,
                              void* d_out, int out_size)
{
    const float* X   = (const float*)d_in[0];
    const float* W1  = (const float*)d_in[1];
    const float* b1  = (const float*)d_in[2];
    const float* g1  = (const float*)d_in[3];
    const float* be1 = (const float*)d_in[4];
    const float* W2  = (const float*)d_in[5];
    const float* b2  = (const float*)d_in[6];
    const float* g2  = (const float*)d_in[7];
    const float* be2 = (const float*)d_in[8];
    const float* W3  = (const float*)d_in[9];
    const float* b3  = (const float*)d_in[10];
    const int*   batch = (const int*)d_in[11];
    float* outp = (float*)d_out;

    __half *h1, *h2, *xh, *w1t, *w2t, *w3t;
    cudaGetSymbolAddress((void**)&h1,  g_h1);
    cudaGetSymbolAddress((void**)&h2,  g_h2);
    cudaGetSymbolAddress((void**)&xh,  g_xh);
    cudaGetSymbolAddress((void**)&w1t, g_w1t);
    cudaGetSymbolAddress((void**)&w2t, g_w2t);
    cudaGetSymbolAddress((void**)&w3t, g_w3t);

    cudaFuncSetAttribute(h_gemm<0>,
        cudaFuncAttributeMaxDynamicSharedMemorySize, GEMM_SMEM);
    cudaFuncSetAttribute(h_gemm<1>,
        cudaFuncAttributeMaxDynamicSharedMemorySize, GEMM_SMEM);

    // 1: X -> fp16
    cvt_x_kernel<<<(N_ROWS * D_IN / 4 + 255) / 256, 256>>>(X, xh, N_ROWS * D_IN / 4);
    // 2-3: W1,W2 transpose -> fp16 [N][K]
    wtrans_kernel<<<dim3(D_H / 32, D_IN / 32), 256>>>(W1, w1t, D_IN, D_H);
    wtrans_kernel<<<dim3(D_H / 32, D_H  / 32), 256>>>(W2, w2t, D_H,  D_H);

    // 4: layer 1  h1 = relu(X @ W1 + b1)
    h_gemm<0><<<dim3(D_H / 128, N_ROWS / 256), 512, GEMM_SMEM>>>(
        xh, w1t, b1, h1, D_IN, D_IN, D_H, nullptr, nullptr);
    // 5: LN1
    ln_kernel<<<N_ROWS, 256>>>(h1, g1, be1);

    // 6: layer 2  h2 = relu(h1 @ W2 + b2)   [ncu capture target]
    h_gemm<0><<<dim3(D_H / 128, N_ROWS / 256), 512, GEMM_SMEM>>>(
        h1, w2t, b2, h2, D_H, D_H, D_H, nullptr, nullptr);
    // 7: LN2
    ln_kernel<<<N_ROWS, 256>>>(h2, g2, be2);

    // 8: W3 transpose; 9: zero out+counts; 10: per-group counts
    wtrans_kernel<<<dim3(D_OUT / 32, D_H / 32), 256>>>(W3, w3t, D_H, D_OUT);
    zero_kernel<<<(NUM_GROUPS * D_OUT + 255) / 256, 256>>>(outp);
    count_kernel<<<(N_ROWS + 255) / 256, 256>>>(batch);

    // 11: layer 3 + segment-sum atomics
    h_gemm<1><<<dim3(1, N_ROWS / 256), 512, GEMM_SMEM>>>(
        h2, w3t, b3, nullptr, D_H, D_H, D_OUT, batch, outp);

    // 12: mean = sum / count
    finalize_kernel<<<(NUM_GROUPS * D_OUT + 255) / 256, 256>>>(outp);
}

// round 8
// speedup vs baseline: 1.8770x; 1.1239x over previous
#include <cuda_runtime.h>
#include <cuda_fp16.h>
#include <cstdint>

// ---------------------------------------------------------------------------
// Problem constants
// ---------------------------------------------------------------------------
#define N_ROWS     131072
#define D_IN       512
#define D_H        1024
#define D_OUT      128
#define NUM_GROUPS 1024
#define LN_EPS     1e-5f

// ---------------------------------------------------------------------------
// Device scratch (no cudaMalloc allowed)
// ---------------------------------------------------------------------------
__device__ __half g_h1[(size_t)N_ROWS * D_H];   // layer1 act (post-LN, fp16)
__device__ __half g_h2[(size_t)N_ROWS * D_H];   // layer2 act (post-LN, fp16)
__device__ __half g_xh[(size_t)N_ROWS * D_IN];  // X in fp16
__device__ __half g_w1t[(size_t)D_H * D_IN];    // W1^T [N][K] fp16
__device__ __half g_w2t[(size_t)D_H * D_H];     // W2^T [N][K] fp16
__device__ __half g_w3t[(size_t)D_OUT * D_H];   // W3^T [N][K] fp16
__device__ float  g_counts[NUM_GROUPS];

// ---------------------------------------------------------------------------
// Helpers
// ---------------------------------------------------------------------------
__device__ __forceinline__ uint32_t smem_u32(const void* p) {
    uint32_t a;
    asm("{ .reg .u64 t; cvta.to.shared.u64 t, %1; cvt.u32.u64 %0, t; }"
        : "=r"(a) : "l"(p));
    return a;
}
__device__ __forceinline__ void cp_async16(uint32_t dst, const void* src) {
    asm volatile("cp.async.cg.shared.global [%0], [%1], 16;\n"
                 :: "r"(dst), "l"(src));
}
__device__ __forceinline__ void cp_commit() {
    asm volatile("cp.async.commit_group;\n" ::);
}
template <int N>
__device__ __forceinline__ void cp_wait() {
    asm volatile("cp.async.wait_group %0;\n" :: "n"(N));
}

__device__ __forceinline__ void ldm_x4(uint32_t* r, uint32_t addr) {
    asm volatile(
        "ldmatrix.sync.aligned.m8n8.x4.shared.b16 {%0,%1,%2,%3}, [%4];"
        : "=r"(r[0]), "=r"(r[1]), "=r"(r[2]), "=r"(r[3]) : "r"(addr));
}

__device__ __forceinline__ void mma_f16(float* c, const uint32_t* a, const uint32_t* b) {
    asm volatile(
        "mma.sync.aligned.m16n8k16.row.col.f32.f16.f16.f32 "
        "{%0,%1,%2,%3}, {%4,%5,%6,%7}, {%8,%9}, {%0,%1,%2,%3};\n"
        : "+f"(c[0]), "+f"(c[1]), "+f"(c[2]), "+f"(c[3])
        : "r"(a[0]), "r"(a[1]), "r"(a[2]), "r"(a[3]), "r"(b[0]), "r"(b[1]));
}

// ---------------------------------------------------------------------------
// FP16 tensor-core GEMM: C[M,Nc] = A[M,K] @ Bt[Nc,K]^T + bias
//   EPI == 0 : C(half) = relu(.), row-major ldc
//   EPI == 1 : atomicAdd into out[batch[row]*D_OUT + col] (fp32 segment sum)
// BM=256, BN=128, BK=64, 512 threads, 16 warps (4x4), warp tile 64x32,
// per-warp 4x4 m16n8k16 fragments loaded via ldmatrix.x4,
// 3-stage cp.async pipeline with ONE __syncthreads per iteration
// (load of stage (it+2)%3 is issued after the barrier; its last readers
//  were at iter it-1 and every warp past the barrier finished it-1).
// SMEM rows padded to 72 halves (144 B) -> conflict-free ldmatrix phases.
// Requires M%256==0, Nc==128, K%64==0.
// ---------------------------------------------------------------------------
#define A_HALVES 18432                 // 256*72
#define A_BYTES2 36864
#define STG_B    55296                 // A_BYTES2 + 128*72*2
#define GEMM_SMEM (3 * STG_B)          // 165888

template <int EPI>
__global__ void __launch_bounds__(512, 1)
h_gemm(const __half* __restrict__ A,
       const __half* __restrict__ Bt,
       const float* __restrict__ bias,
       __half* __restrict__ C,
       int K, int lda, int ldc,
       const int* __restrict__ batch,
       float* __restrict__ out)
{
    extern __shared__ char smem[];
    const uint32_t sb = smem_u32(smem);

    const int tid = threadIdx.x;
    const int wid = tid >> 5, lane = tid & 31;
    const int wm = wid >> 2;            // 0..3 -> 64 rows
    const int wn = wid & 3;             // 0..3 -> 32 cols
    const int t  = lane & 3;            // 0..3

    const int m0 = blockIdx.y * 256;
    const int n0 = blockIdx.x * 128;

    // ldmatrix per-lane byte offsets (relative to tile base)
    // A fragment i (16x16): row = wm*64 + i*16 + (lane&15), k-half = lane>>4
    uint32_t a_off[4];
    {
        const int lrow = lane & 15, lk = (lane >> 4) & 1;
        #pragma unroll
        for (int i = 0; i < 4; i++)
            a_off[i] = (uint32_t)(((wm * 64 + i * 16 + lrow) * 72 + lk * 8) * 2);
    }
    // B pair jj (covers j=2jj,2jj+1): grp=lane>>3: matrix {j-lo, j-hi, j+1-lo, j+1-hi}
    uint32_t b_off[2];
    {
        const int grp = lane >> 3;              // 0..3
        const int bj = grp >> 1, bk = (grp & 1) * 8;
        #pragma unroll
        for (int jj = 0; jj < 2; jj++)
            b_off[jj] = (uint32_t)(((wn * 32 + (2 * jj + bj) * 8 + (lane & 7)) * 72 + bk) * 2);
    }

    float acc[4][4][4];
    #pragma unroll
    for (int i = 0; i < 4; i++)
        #pragma unroll
        for (int j = 0; j < 4; j++)
            #pragma unroll
            for (int r = 0; r < 4; r++) acc[i][j][r] = 0.f;

    const __half* Arow = A  + (size_t)m0 * lda;
    const __half* Brow = Bt + (size_t)n0 * K;

    auto load_stage = [&](int k0, int s) {   // k0 in halves
        const uint32_t base = sb + s * STG_B;
        #pragma unroll
        for (int c = 0; c < 4; c++) {        // A: 2048 16B chunks
            int chunk = tid + c * 512;
            int row = chunk >> 3, k16 = chunk & 7;
            cp_async16(base + row * 144 + k16 * 16,
                       Arow + (size_t)row * lda + k0 + k16 * 8);
        }
        #pragma unroll
        for (int c = 0; c < 2; c++) {        // B: 1024 16B chunks
            int chunk = tid + c * 512;
            int row = chunk >> 3, k16 = chunk & 7;
            cp_async16(base + A_BYTES2 + row * 144 + k16 * 16,
                       Brow + (size_t)row * K + k0 + k16 * 8);
        }
        cp_commit();
    };

    const int iters = K >> 6;
    load_stage(0, 0);
    load_stage(64, 1);

    for (int it = 0; it < iters; it++) {
        if (it + 1 < iters) cp_wait<1>();
        else                cp_wait<0>();
        __syncthreads();
        if (it + 2 < iters) load_stage((it + 2) * 64, (it + 2) % 3);

        const uint32_t sA = sb + (it % 3) * STG_B;
        const uint32_t sB = sA + A_BYTES2;

        #pragma unroll
        for (int ko = 0; ko < 4; ko++) {     // 4 x k16 per BK=64
            const uint32_t koff = ko * 32;   // 16 halves = 32 bytes
            uint32_t a[4][4], b[2][4];
            #pragma unroll
            for (int i = 0; i < 4; i++) ldm_x4(a[i], sA + a_off[i] + koff);
            ldm_x4(b[0], sB + b_off[0] + koff);
            ldm_x4(b[1], sB + b_off[1] + koff);
            #pragma unroll
            for (int i = 0; i < 4; i++)
                #pragma unroll
                for (int j = 0; j < 4; j++)
                    mma_f16(acc[i][j], a[i], &b[j >> 1][(j & 1) * 2]);
        }
    }

    // bias values: cols n0 + wn*32 + j*8 + 2t, +1
    const int g = lane >> 2;
    float bv[4][2];
    #pragma unroll
    for (int j = 0; j < 4; j++) {
        int col = n0 + wn * 32 + j * 8 + 2 * t;
        bv[j][0] = bias[col];
        bv[j][1] = bias[col + 1];
    }

    if (EPI == 0) {
        #pragma unroll
        for (int i = 0; i < 4; i++) {
            int r0 = m0 + wm * 64 + i * 16 + g;
            __half* c0 = C + (size_t)r0 * ldc + n0;
            __half* c1 = C + (size_t)(r0 + 8) * ldc + n0;
            #pragma unroll
            for (int j = 0; j < 4; j++) {
                int col = wn * 32 + j * 8 + 2 * t;
                *(__half2*)(c0 + col) = __floats2half2_rn(
                    fmaxf(acc[i][j][0] + bv[j][0], 0.f),
                    fmaxf(acc[i][j][1] + bv[j][1], 0.f));
                *(__half2*)(c1 + col) = __floats2half2_rn(
                    fmaxf(acc[i][j][2] + bv[j][0], 0.f),
                    fmaxf(acc[i][j][3] + bv[j][1], 0.f));
            }
        }
    } else {
        #pragma unroll
        for (int i = 0; i < 4; i++) {
            int r0 = m0 + wm * 64 + i * 16 + g;
            int q0 = batch[r0], q1 = batch[r0 + 8];
            float* o0 = out + (size_t)q0 * D_OUT;
            float* o1 = out + (size_t)q1 * D_OUT;
            #pragma unroll
            for (int j = 0; j < 4; j++) {
                int col = wn * 32 + j * 8 + 2 * t;   // n0 == 0 here
                atomicAdd(o0 + col,     acc[i][j][0] + bv[j][0]);
                atomicAdd(o0 + col + 1, acc[i][j][1] + bv[j][1]);
                atomicAdd(o1 + col,     acc[i][j][2] + bv[j][0]);
                atomicAdd(o1 + col + 1, acc[i][j][3] + bv[j][1]);
            }
        }
    }
}

// ---------------------------------------------------------------------------
// In-place row LayerNorm over D_H=1024 fp16; stats in fp32.
// ---------------------------------------------------------------------------
__global__ void __launch_bounds__(256)
ln_kernel(__half* __restrict__ X,
          const float* __restrict__ gamma,
          const float* __restrict__ beta)
{
    const int row = blockIdx.x;
    const int tid = threadIdx.x;
    __half* x = X + (size_t)row * D_H;

    uint2 u = *(const uint2*)(x + tid * 4);
    float2 p0 = __half22float2(*(__half2*)&u.x);
    float2 p1 = __half22float2(*(__half2*)&u.y);
    float s  = p0.x + p0.y + p1.x + p1.y;
    float sq = p0.x * p0.x + p0.y * p0.y + p1.x * p1.x + p1.y * p1.y;

    #pragma unroll
    for (int o = 16; o > 0; o >>= 1) {
        s  += __shfl_xor_sync(0xffffffffu, s, o);
        sq += __shfl_xor_sync(0xffffffffu, sq, o);
    }
    __shared__ float2 red[8];
    const int w = tid >> 5, l = tid & 31;
    if (l == 0) red[w] = make_float2(s, sq);
    __syncthreads();
    if (w == 0) {
        float2 p = (l < 8) ? red[l] : make_float2(0.f, 0.f);
        s = p.x; sq = p.y;
        #pragma unroll
        for (int o = 4; o > 0; o >>= 1) {
            s  += __shfl_xor_sync(0xffffffffu, s, o);
            sq += __shfl_xor_sync(0xffffffffu, sq, o);
        }
        if (l == 0) red[0] = make_float2(s, sq);
    }
    __syncthreads();

    const float mean = red[0].x * (1.0f / D_H);
    const float var  = red[0].y * (1.0f / D_H) - mean * mean;
    const float inv  = rsqrtf(var + LN_EPS);

    float4 gg = *(const float4*)(gamma + tid * 4);
    float4 bb = *(const float4*)(beta  + tid * 4);
    uint2 o;
    *(__half2*)&o.x = __floats2half2_rn((p0.x - mean) * inv * gg.x + bb.x,
                                        (p0.y - mean) * inv * gg.y + bb.y);
    *(__half2*)&o.y = __floats2half2_rn((p1.x - mean) * inv * gg.z + bb.z,
                                        (p1.y - mean) * inv * gg.w + bb.w);
    *(uint2*)(x + tid * 4) = o;
}

// ---------------------------------------------------------------------------
// Small helper kernels
// ---------------------------------------------------------------------------
__global__ void cvt_x_kernel(const float* __restrict__ src,
                             __half* __restrict__ dst, int n4)
{
    int i = blockIdx.x * blockDim.x + threadIdx.x;
    if (i < n4) {
        float4 v = ((const float4*)src)[i];
        uint2 o;
        *(__half2*)&o.x = __floats2half2_rn(v.x, v.y);
        *(__half2*)&o.y = __floats2half2_rn(v.z, v.w);
        ((uint2*)dst)[i] = o;
    }
}

// dst[n*K + k] = fp16(src[k*N + n]); grid (N/32, K/32), 256 threads
__global__ void wtrans_kernel(const float* __restrict__ src,
                              __half* __restrict__ dst, int K, int N)
{
    __shared__ float t[32][33];
    const int n0 = blockIdx.x * 32, k0 = blockIdx.y * 32;
    const int tx = threadIdx.x & 31, ty = threadIdx.x >> 5;
    #pragma unroll
    for (int r = ty; r < 32; r += 8)
        t[r][tx] = src[(size_t)(k0 + r) * N + n0 + tx];
    __syncthreads();
    #pragma unroll
    for (int r = ty; r < 32; r += 8)
        dst[(size_t)(n0 + r) * K + k0 + tx] = __float2half_rn(t[tx][r]);
}

__global__ void zero_kernel(float* __restrict__ out)
{
    int i = blockIdx.x * blockDim.x + threadIdx.x;
    if (i < NUM_GROUPS * D_OUT) out[i] = 0.f;
    if (i < NUM_GROUPS) g_counts[i] = 0.f;
}

__global__ void count_kernel(const int* __restrict__ batch)
{
    int i = blockIdx.x * blockDim.x + threadIdx.x;
    if (i < N_ROWS) atomicAdd(&g_counts[batch[i]], 1.0f);
}

__global__ void finalize_kernel(float* __restrict__ out)
{
    int i = blockIdx.x * blockDim.x + threadIdx.x;
    if (i < NUM_GROUPS * D_OUT) out[i] = out[i] / g_counts[i / D_OUT];
}

// ---------------------------------------------------------------------------
// kernel_launch
// Inputs: X, W1, b1, g1, be1, W2, b2, g2, be2, W3, b3, all_batch
// Layer-2 GEMM is the 6th launch (ncu -s 5 -c 1 captures it).
// ---------------------------------------------------------------------------
extern "C" void kernel_launch(void* const* d_in, const int* in_sizes, int n_in,
                              void* d_out, int out_size)
{
    const float* X   = (const float*)d_in[0];
    const float* W1  = (const float*)d_in[1];
    const float* b1  = (const float*)d_in[2];
    const float* g1  = (const float*)d_in[3];
    const float* be1 = (const float*)d_in[4];
    const float* W2  = (const float*)d_in[5];
    const float* b2  = (const float*)d_in[6];
    const float* g2  = (const float*)d_in[7];
    const float* be2 = (const float*)d_in[8];
    const float* W3  = (const float*)d_in[9];
    const float* b3  = (const float*)d_in[10];
    const int*   batch = (const int*)d_in[11];
    float* outp = (float*)d_out;

    __half *h1, *h2, *xh, *w1t, *w2t, *w3t;
    cudaGetSymbolAddress((void**)&h1,  g_h1);
    cudaGetSymbolAddress((void**)&h2,  g_h2);
    cudaGetSymbolAddress((void**)&xh,  g_xh);
    cudaGetSymbolAddress((void**)&w1t, g_w1t);
    cudaGetSymbolAddress((void**)&w2t, g_w2t);
    cudaGetSymbolAddress((void**)&w3t, g_w3t);

    cudaFuncSetAttribute(h_gemm<0>,
        cudaFuncAttributeMaxDynamicSharedMemorySize, GEMM_SMEM);
    cudaFuncSetAttribute(h_gemm<1>,
        cudaFuncAttributeMaxDynamicSharedMemorySize, GEMM_SMEM);

    // 1: X -> fp16
    cvt_x_kernel<<<(N_ROWS * D_IN / 4 + 255) / 256, 256>>>(X, xh, N_ROWS * D_IN / 4);
    // 2-3: W1,W2 transpose -> fp16 [N][K]
    wtrans_kernel<<<dim3(D_H / 32, D_IN / 32), 256>>>(W1, w1t, D_IN, D_H);
    wtrans_kernel<<<dim3(D_H / 32, D_H  / 32), 256>>>(W2, w2t, D_H,  D_H);

    // 4: layer 1  h1 = relu(X @ W1 + b1)
    h_gemm<0><<<dim3(D_H / 128, N_ROWS / 256), 512, GEMM_SMEM>>>(
        xh, w1t, b1, h1, D_IN, D_IN, D_H, nullptr, nullptr);
    // 5: LN1
    ln_kernel<<<N_ROWS, 256>>>(h1, g1, be1);

    // 6: layer 2  h2 = relu(h1 @ W2 + b2)   [ncu capture target]
    h_gemm<0><<<dim3(D_H / 128, N_ROWS / 256), 512, GEMM_SMEM>>>(
        h1, w2t, b2, h2, D_H, D_H, D_H, nullptr, nullptr);
    // 7: LN2
    ln_kernel<<<N_ROWS, 256>>>(h2, g2, be2);

    // 8: W3 transpose; 9: zero out+counts; 10: per-group counts
    wtrans_kernel<<<dim3(D_OUT / 32, D_H / 32), 256>>>(W3, w3t, D_H, D_OUT);
    zero_kernel<<<(NUM_GROUPS * D_OUT + 255) / 256, 256>>>(outp);
    count_kernel<<<(N_ROWS + 255) / 256, 256>>>(batch);

    // 11: layer 3 + segment-sum atomics
    h_gemm<1><<<dim3(1, N_ROWS / 256), 512, GEMM_SMEM>>>(
        h2, w3t, b3, nullptr, D_H, D_H, D_OUT, batch, outp);

    // 12: mean = sum / count
    finalize_kernel<<<(NUM_GROUPS * D_OUT + 255) / 256, 256>>>(outp);
}

// round 9
// speedup vs baseline: 1.9626x; 1.0456x over previous
#include <cuda_runtime.h>
#include <cuda_fp16.h>
#include <cstdint>

// ---------------------------------------------------------------------------
// Problem constants
// ---------------------------------------------------------------------------
#define N_ROWS     131072
#define D_IN       512
#define D_H        1024
#define D_OUT      128
#define NUM_GROUPS 1024
#define LN_EPS     1e-5f

// ---------------------------------------------------------------------------
// Device scratch (no cudaMalloc allowed)
// ---------------------------------------------------------------------------
__device__ __half g_h1[(size_t)N_ROWS * D_H];   // layer1 act (post-LN, fp16)
__device__ __half g_h2[(size_t)N_ROWS * D_H];   // layer2 act (post-LN, fp16)
__device__ __half g_xh[(size_t)N_ROWS * D_IN];  // X in fp16
__device__ __half g_w1t[(size_t)D_H * D_IN];    // W1^T [N][K] fp16
__device__ __half g_w2t[(size_t)D_H * D_H];     // W2^T [N][K] fp16
__device__ __half g_w3t[(size_t)D_OUT * D_H];   // W3^T [N][K] fp16
__device__ float  g_counts[NUM_GROUPS];

// ---------------------------------------------------------------------------
// Helpers
// ---------------------------------------------------------------------------
__device__ __forceinline__ uint32_t smem_u32(const void* p) {
    uint32_t a;
    asm("{ .reg .u64 t; cvta.to.shared.u64 t, %1; cvt.u32.u64 %0, t; }"
        : "=r"(a) : "l"(p));
    return a;
}
__device__ __forceinline__ void cp_async16(uint32_t dst, const void* src) {
    asm volatile("cp.async.cg.shared.global [%0], [%1], 16;\n"
                 :: "r"(dst), "l"(src));
}
__device__ __forceinline__ void cp_commit() {
    asm volatile("cp.async.commit_group;\n" ::);
}
template <int N>
__device__ __forceinline__ void cp_wait() {
    asm volatile("cp.async.wait_group %0;\n" :: "n"(N));
}

__device__ __forceinline__ void ldm_x4(uint32_t* r, uint32_t addr) {
    asm volatile(
        "ldmatrix.sync.aligned.m8n8.x4.shared.b16 {%0,%1,%2,%3}, [%4];"
        : "=r"(r[0]), "=r"(r[1]), "=r"(r[2]), "=r"(r[3]) : "r"(addr));
}

__device__ __forceinline__ void mma_f16(float* c, const uint32_t* a, const uint32_t* b) {
    asm volatile(
        "mma.sync.aligned.m16n8k16.row.col.f32.f16.f16.f32 "
        "{%0,%1,%2,%3}, {%4,%5,%6,%7}, {%8,%9}, {%0,%1,%2,%3};\n"
        : "+f"(c[0]), "+f"(c[1]), "+f"(c[2]), "+f"(c[3])
        : "r"(a[0]), "r"(a[1]), "r"(a[2]), "r"(a[3]), "r"(b[0]), "r"(b[1]));
}

// ---------------------------------------------------------------------------
// FP16 tensor-core GEMM: C[M,Nc] = A[M,K] @ Bt[Nc,K]^T + bias
//   EPI == 0 : C(half) = relu(.), row-major ldc
//   EPI == 1 : atomicAdd into out[batch[row]*D_OUT + col] (fp32 segment sum)
// BM=128, BN=128, BK=64, 256 threads, 8 warps (2x4), warp tile 64x32,
// __launch_bounds__(256,2) -> 2 CTAs/SM: two independent barrier domains
// keep the HMMA pipe fed across syncthreads/epilogue phases.
// Fragments via ldmatrix.x4; 3-stage cp.async; ONE barrier per iteration.
// SMEM rows padded to 72 halves (144 B) -> conflict-free ldmatrix phases.
// Requires M%128==0, Nc==128, K%64==0.
// ---------------------------------------------------------------------------
#define A_HALVES 9216                  // 128*72
#define A_BYTES2 18432
#define STG_B    36864                 // A_BYTES2 + 128*72*2
#define GEMM_SMEM (3 * STG_B)          // 110592

template <int EPI>
__global__ void __launch_bounds__(256, 2)
h_gemm(const __half* __restrict__ A,
       const __half* __restrict__ Bt,
       const float* __restrict__ bias,
       __half* __restrict__ C,
       int K, int lda, int ldc,
       const int* __restrict__ batch,
       float* __restrict__ out)
{
    extern __shared__ char smem[];
    const uint32_t sb = smem_u32(smem);

    const int tid = threadIdx.x;
    const int wid = tid >> 5, lane = tid & 31;
    const int wm = wid >> 2;            // 0..1 -> 64 rows
    const int wn = wid & 3;             // 0..3 -> 32 cols
    const int t  = lane & 3;            // 0..3

    const int m0 = blockIdx.y * 128;
    const int n0 = blockIdx.x * 128;

    // ldmatrix per-lane byte offsets (relative to tile base)
    // A fragment i (16x16): row = wm*64 + i*16 + (lane&15), k-half = lane>>4
    uint32_t a_off[4];
    {
        const int lrow = lane & 15, lk = (lane >> 4) & 1;
        #pragma unroll
        for (int i = 0; i < 4; i++)
            a_off[i] = (uint32_t)(((wm * 64 + i * 16 + lrow) * 72 + lk * 8) * 2);
    }
    // B pair jj (covers j=2jj,2jj+1): grp=lane>>3: matrix {j-lo, j-hi, j+1-lo, j+1-hi}
    uint32_t b_off[2];
    {
        const int grp = lane >> 3;              // 0..3
        const int bj = grp >> 1, bk = (grp & 1) * 8;
        #pragma unroll
        for (int jj = 0; jj < 2; jj++)
            b_off[jj] = (uint32_t)(((wn * 32 + (2 * jj + bj) * 8 + (lane & 7)) * 72 + bk) * 2);
    }

    float acc[4][4][4];
    #pragma unroll
    for (int i = 0; i < 4; i++)
        #pragma unroll
        for (int j = 0; j < 4; j++)
            #pragma unroll
            for (int r = 0; r < 4; r++) acc[i][j][r] = 0.f;

    const __half* Arow = A  + (size_t)m0 * lda;
    const __half* Brow = Bt + (size_t)n0 * K;

    auto load_stage = [&](int k0, int s) {   // k0 in halves
        const uint32_t base = sb + s * STG_B;
        #pragma unroll
        for (int c = 0; c < 4; c++) {        // A: 1024 16B chunks
            int chunk = tid + c * 256;
            int row = chunk >> 3, k16 = chunk & 7;
            cp_async16(base + row * 144 + k16 * 16,
                       Arow + (size_t)row * lda + k0 + k16 * 8);
        }
        #pragma unroll
        for (int c = 0; c < 4; c++) {        // B: 1024 16B chunks
            int chunk = tid + c * 256;
            int row = chunk >> 3, k16 = chunk & 7;
            cp_async16(base + A_BYTES2 + row * 144 + k16 * 16,
                       Brow + (size_t)row * K + k0 + k16 * 8);
        }
        cp_commit();
    };

    const int iters = K >> 6;
    load_stage(0, 0);
    load_stage(64, 1);

    for (int it = 0; it < iters; it++) {
        if (it + 1 < iters) cp_wait<1>();
        else                cp_wait<0>();
        __syncthreads();
        if (it + 2 < iters) load_stage((it + 2) * 64, (it + 2) % 3);

        const uint32_t sA = sb + (it % 3) * STG_B;
        const uint32_t sB = sA + A_BYTES2;

        #pragma unroll
        for (int ko = 0; ko < 4; ko++) {     // 4 x k16 per BK=64
            const uint32_t koff = ko * 32;   // 16 halves = 32 bytes
            uint32_t a[4][4], b[2][4];
            #pragma unroll
            for (int i = 0; i < 4; i++) ldm_x4(a[i], sA + a_off[i] + koff);
            ldm_x4(b[0], sB + b_off[0] + koff);
            ldm_x4(b[1], sB + b_off[1] + koff);
            #pragma unroll
            for (int i = 0; i < 4; i++)
                #pragma unroll
                for (int j = 0; j < 4; j++)
                    mma_f16(acc[i][j], a[i], &b[j >> 1][(j & 1) * 2]);
        }
    }

    // bias values: cols n0 + wn*32 + j*8 + 2t, +1
    const int g = lane >> 2;
    float bv[4][2];
    #pragma unroll
    for (int j = 0; j < 4; j++) {
        int col = n0 + wn * 32 + j * 8 + 2 * t;
        bv[j][0] = bias[col];
        bv[j][1] = bias[col + 1];
    }

    if (EPI == 0) {
        #pragma unroll
        for (int i = 0; i < 4; i++) {
            int r0 = m0 + wm * 64 + i * 16 + g;
            __half* c0 = C + (size_t)r0 * ldc + n0;
            __half* c1 = C + (size_t)(r0 + 8) * ldc + n0;
            #pragma unroll
            for (int j = 0; j < 4; j++) {
                int col = wn * 32 + j * 8 + 2 * t;
                *(__half2*)(c0 + col) = __floats2half2_rn(
                    fmaxf(acc[i][j][0] + bv[j][0], 0.f),
                    fmaxf(acc[i][j][1] + bv[j][1], 0.f));
                *(__half2*)(c1 + col) = __floats2half2_rn(
                    fmaxf(acc[i][j][2] + bv[j][0], 0.f),
                    fmaxf(acc[i][j][3] + bv[j][1], 0.f));
            }
        }
    } else {
        #pragma unroll
        for (int i = 0; i < 4; i++) {
            int r0 = m0 + wm * 64 + i * 16 + g;
            int q0 = batch[r0], q1 = batch[r0 + 8];
            float* o0 = out + (size_t)q0 * D_OUT;
            float* o1 = out + (size_t)q1 * D_OUT;
            #pragma unroll
            for (int j = 0; j < 4; j++) {
                int col = wn * 32 + j * 8 + 2 * t;   // n0 == 0 here
                atomicAdd(o0 + col,     acc[i][j][0] + bv[j][0]);
                atomicAdd(o0 + col + 1, acc[i][j][1] + bv[j][1]);
                atomicAdd(o1 + col,     acc[i][j][2] + bv[j][0]);
                atomicAdd(o1 + col + 1, acc[i][j][3] + bv[j][1]);
            }
        }
    }
}

// ---------------------------------------------------------------------------
// In-place row LayerNorm over D_H=1024 fp16; stats in fp32.
// ---------------------------------------------------------------------------
__global__ void __launch_bounds__(256)
ln_kernel(__half* __restrict__ X,
          const float* __restrict__ gamma,
          const float* __restrict__ beta)
{
    const int row = blockIdx.x;
    const int tid = threadIdx.x;
    __half* x = X + (size_t)row * D_H;

    uint2 u = *(const uint2*)(x + tid * 4);
    float2 p0 = __half22float2(*(__half2*)&u.x);
    float2 p1 = __half22float2(*(__half2*)&u.y);
    float s  = p0.x + p0.y + p1.x + p1.y;
    float sq = p0.x * p0.x + p0.y * p0.y + p1.x * p1.x + p1.y * p1.y;

    #pragma unroll
    for (int o = 16; o > 0; o >>= 1) {
        s  += __shfl_xor_sync(0xffffffffu, s, o);
        sq += __shfl_xor_sync(0xffffffffu, sq, o);
    }
    __shared__ float2 red[8];
    const int w = tid >> 5, l = tid & 31;
    if (l == 0) red[w] = make_float2(s, sq);
    __syncthreads();
    if (w == 0) {
        float2 p = (l < 8) ? red[l] : make_float2(0.f, 0.f);
        s = p.x; sq = p.y;
        #pragma unroll
        for (int o = 4; o > 0; o >>= 1) {
            s  += __shfl_xor_sync(0xffffffffu, s, o);
            sq += __shfl_xor_sync(0xffffffffu, sq, o);
        }
        if (l == 0) red[0] = make_float2(s, sq);
    }
    __syncthreads();

    const float mean = red[0].x * (1.0f / D_H);
    const float var  = red[0].y * (1.0f / D_H) - mean * mean;
    const float inv  = rsqrtf(var + LN_EPS);

    float4 gg = *(const float4*)(gamma + tid * 4);
    float4 bb = *(const float4*)(beta  + tid * 4);
    uint2 o;
    *(__half2*)&o.x = __floats2half2_rn((p0.x - mean) * inv * gg.x + bb.x,
                                        (p0.y - mean) * inv * gg.y + bb.y);
    *(__half2*)&o.y = __floats2half2_rn((p1.x - mean) * inv * gg.z + bb.z,
                                        (p1.y - mean) * inv * gg.w + bb.w);
    *(uint2*)(x + tid * 4) = o;
}

// ---------------------------------------------------------------------------
// Small helper kernels
// ---------------------------------------------------------------------------
__global__ void cvt_x_kernel(const float* __restrict__ src,
                             __half* __restrict__ dst, int n4)
{
    int i = blockIdx.x * blockDim.x + threadIdx.x;
    if (i < n4) {
        float4 v = ((const float4*)src)[i];
        uint2 o;
        *(__half2*)&o.x = __floats2half2_rn(v.x, v.y);
        *(__half2*)&o.y = __floats2half2_rn(v.z, v.w);
        ((uint2*)dst)[i] = o;
    }
}

// dst[n*K + k] = fp16(src[k*N + n]); grid (N/32, K/32), 256 threads
__global__ void wtrans_kernel(const float* __restrict__ src,
                              __half* __restrict__ dst, int K, int N)
{
    __shared__ float t[32][33];
    const int n0 = blockIdx.x * 32, k0 = blockIdx.y * 32;
    const int tx = threadIdx.x & 31, ty = threadIdx.x >> 5;
    #pragma unroll
    for (int r = ty; r < 32; r += 8)
        t[r][tx] = src[(size_t)(k0 + r) * N + n0 + tx];
    __syncthreads();
    #pragma unroll
    for (int r = ty; r < 32; r += 8)
        dst[(size_t)(n0 + r) * K + k0 + tx] = __float2half_rn(t[tx][r]);
}

__global__ void zero_kernel(float* __restrict__ out)
{
    int i = blockIdx.x * blockDim.x + threadIdx.x;
    if (i < NUM_GROUPS * D_OUT) out[i] = 0.f;
    if (i < NUM_GROUPS) g_counts[i] = 0.f;
}

__global__ void count_kernel(const int* __restrict__ batch)
{
    int i = blockIdx.x * blockDim.x + threadIdx.x;
    if (i < N_ROWS) atomicAdd(&g_counts[batch[i]], 1.0f);
}

__global__ void finalize_kernel(float* __restrict__ out)
{
    int i = blockIdx.x * blockDim.x + threadIdx.x;
    if (i < NUM_GROUPS * D_OUT) out[i] = out[i] / g_counts[i / D_OUT];
}

// ---------------------------------------------------------------------------
// kernel_launch
// Inputs: X, W1, b1, g1, be1, W2, b2, g2, be2, W3, b3, all_batch
// Layer-2 GEMM is the 6th launch (ncu -s 5 -c 1 captures it).
// ---------------------------------------------------------------------------
extern "C" void kernel_launch(void* const* d_in, const int* in_sizes, int n_in,
                              void* d_out, int out_size)
{
    const float* X   = (const float*)d_in[0];
    const float* W1  = (const float*)d_in[1];
    const float* b1  = (const float*)d_in[2];
    const float* g1  = (const float*)d_in[3];
    const float* be1 = (const float*)d_in[4];
    const float* W2  = (const float*)d_in[5];
    const float* b2  = (const float*)d_in[6];
    const float* g2  = (const float*)d_in[7];
    const float* be2 = (const float*)d_in[8];
    const float* W3  = (const float*)d_in[9];
    const float* b3  = (const float*)d_in[10];
    const int*   batch = (const int*)d_in[11];
    float* outp = (float*)d_out;

    __half *h1, *h2, *xh, *w1t, *w2t, *w3t;
    cudaGetSymbolAddress((void**)&h1,  g_h1);
    cudaGetSymbolAddress((void**)&h2,  g_h2);
    cudaGetSymbolAddress((void**)&xh,  g_xh);
    cudaGetSymbolAddress((void**)&w1t, g_w1t);
    cudaGetSymbolAddress((void**)&w2t, g_w2t);
    cudaGetSymbolAddress((void**)&w3t, g_w3t);

    cudaFuncSetAttribute(h_gemm<0>,
        cudaFuncAttributeMaxDynamicSharedMemorySize, GEMM_SMEM);
    cudaFuncSetAttribute(h_gemm<1>,
        cudaFuncAttributeMaxDynamicSharedMemorySize, GEMM_SMEM);

    // 1: X -> fp16
    cvt_x_kernel<<<(N_ROWS * D_IN / 4 + 255) / 256, 256>>>(X, xh, N_ROWS * D_IN / 4);
    // 2-3: W1,W2 transpose -> fp16 [N][K]
    wtrans_kernel<<<dim3(D_H / 32, D_IN / 32), 256>>>(W1, w1t, D_IN, D_H);
    wtrans_kernel<<<dim3(D_H / 32, D_H  / 32), 256>>>(W2, w2t, D_H,  D_H);

    // 4: layer 1  h1 = relu(X @ W1 + b1)
    h_gemm<0><<<dim3(D_H / 128, N_ROWS / 128), 256, GEMM_SMEM>>>(
        xh, w1t, b1, h1, D_IN, D_IN, D_H, nullptr, nullptr);
    // 5: LN1
    ln_kernel<<<N_ROWS, 256>>>(h1, g1, be1);

    // 6: layer 2  h2 = relu(h1 @ W2 + b2)   [ncu capture target]
    h_gemm<0><<<dim3(D_H / 128, N_ROWS / 128), 256, GEMM_SMEM>>>(
        h1, w2t, b2, h2, D_H, D_H, D_H, nullptr, nullptr);
    // 7: LN2
    ln_kernel<<<N_ROWS, 256>>>(h2, g2, be2);

    // 8: W3 transpose; 9: zero out+counts; 10: per-group counts
    wtrans_kernel<<<dim3(D_OUT / 32, D_H / 32), 256>>>(W3, w3t, D_H, D_OUT);
    zero_kernel<<<(NUM_GROUPS * D_OUT + 255) / 256, 256>>>(outp);
    count_kernel<<<(N_ROWS + 255) / 256, 256>>>(batch);

    // 11: layer 3 + segment-sum atomics
    h_gemm<1><<<dim3(1, N_ROWS / 128), 256, GEMM_SMEM>>>(
        h2, w3t, b3, nullptr, D_H, D_H, D_OUT, batch, outp);

    // 12: mean = sum / count
    finalize_kernel<<<(NUM_GROUPS * D_OUT + 255) / 256, 256>>>(outp);
}

// round 10
// speedup vs baseline: 1.9627x; 1.0000x over previous
#include <cuda_runtime.h>
#include <cuda_fp16.h>
#include <cstdint>

// ---------------------------------------------------------------------------
// Problem constants
// ---------------------------------------------------------------------------
#define N_ROWS     131072
#define D_IN       512
#define D_H        1024
#define D_OUT      128
#define NUM_GROUPS 1024
#define LN_EPS     1e-5f

// ---------------------------------------------------------------------------
// Device scratch (no cudaMalloc allowed)
// ---------------------------------------------------------------------------
__device__ __half g_h1[(size_t)N_ROWS * D_H];   // layer1 act (post-LN, fp16)
__device__ __half g_h2[(size_t)N_ROWS * D_H];   // layer2 act (post-LN, fp16)
__device__ __half g_xh[(size_t)N_ROWS * D_IN];  // X in fp16
__device__ __half g_w1t[(size_t)D_H * D_IN];    // W1^T [N][K] fp16
__device__ __half g_w2t[(size_t)D_H * D_H];     // W2^T [N][K] fp16
__device__ __half g_w3t[(size_t)D_OUT * D_H];   // W3^T [N][K] fp16
__device__ float  g_counts[NUM_GROUPS];

// ---------------------------------------------------------------------------
// Helpers
// ---------------------------------------------------------------------------
__device__ __forceinline__ uint32_t smem_u32(const void* p) {
    uint32_t a;
    asm("{ .reg .u64 t; cvta.to.shared.u64 t, %1; cvt.u32.u64 %0, t; }"
        : "=r"(a) : "l"(p));
    return a;
}
__device__ __forceinline__ void cp_async16(uint32_t dst, const void* src) {
    asm volatile("cp.async.cg.shared.global [%0], [%1], 16;\n"
                 :: "r"(dst), "l"(src));
}
__device__ __forceinline__ void cp_commit() {
    asm volatile("cp.async.commit_group;\n" ::);
}
template <int N>
__device__ __forceinline__ void cp_wait() {
    asm volatile("cp.async.wait_group %0;\n" :: "n"(N));
}

__device__ __forceinline__ void ldm_x4(uint32_t* r, uint32_t addr) {
    asm volatile(
        "ldmatrix.sync.aligned.m8n8.x4.shared.b16 {%0,%1,%2,%3}, [%4];"
        : "=r"(r[0]), "=r"(r[1]), "=r"(r[2]), "=r"(r[3]) : "r"(addr));
}

__device__ __forceinline__ void mma_f16(float* c, const uint32_t* a, const uint32_t* b) {
    asm volatile(
        "mma.sync.aligned.m16n8k16.row.col.f32.f16.f16.f32 "
        "{%0,%1,%2,%3}, {%4,%5,%6,%7}, {%8,%9}, {%0,%1,%2,%3};\n"
        : "+f"(c[0]), "+f"(c[1]), "+f"(c[2]), "+f"(c[3])
        : "r"(a[0]), "r"(a[1]), "r"(a[2]), "r"(a[3]), "r"(b[0]), "r"(b[1]));
}

// ---------------------------------------------------------------------------
// FP16 tensor-core GEMM: C[M,Nc] = A[M,K] @ Bt[Nc,K]^T + bias
//   EPI == 0 : C(half) = relu(.), row-major ldc
//   EPI == 1 : atomicAdd into out[batch[row]*D_OUT + col] (fp32 segment sum)
// BM=256, BN=128, BK=64, 256 threads, 8 warps (4x2), warp tile 64x64
// (4x8 m16n8k16 fragments) -> smem reads drop to 128 B per MMA instr,
// relieving the 128 B/cyc LDS crossbar that capped the 64x32 config.
// Fragments via ldmatrix.x4; 3-stage cp.async; ONE barrier per iteration.
// SMEM rows padded to 72 halves (144 B) -> conflict-free ldmatrix phases.
// Requires M%256==0, Nc==128, K%64==0.
// ---------------------------------------------------------------------------
#define A_HALVES 18432                 // 256*72
#define A_BYTES2 36864
#define STG_B    55296                 // A_BYTES2 + 128*72*2
#define GEMM_SMEM (3 * STG_B)          // 165888

template <int EPI>
__global__ void __launch_bounds__(256, 1)
h_gemm(const __half* __restrict__ A,
       const __half* __restrict__ Bt,
       const float* __restrict__ bias,
       __half* __restrict__ C,
       int K, int lda, int ldc,
       const int* __restrict__ batch,
       float* __restrict__ out)
{
    extern __shared__ char smem[];
    const uint32_t sb = smem_u32(smem);

    const int tid = threadIdx.x;
    const int wid = tid >> 5, lane = tid & 31;
    const int wm = wid >> 1;            // 0..3 -> 64 rows
    const int wn = wid & 1;             // 0..1 -> 64 cols
    const int t  = lane & 3;            // 0..3

    const int m0 = blockIdx.y * 256;
    const int n0 = blockIdx.x * 128;

    // ldmatrix per-lane byte offsets (relative to tile base)
    // A fragment i (16x16): row = wm*64 + i*16 + (lane&15), k-half = lane>>4
    uint32_t a_off[4];
    {
        const int lrow = lane & 15, lk = (lane >> 4) & 1;
        #pragma unroll
        for (int i = 0; i < 4; i++)
            a_off[i] = (uint32_t)(((wm * 64 + i * 16 + lrow) * 72 + lk * 8) * 2);
    }
    // B pair jj (covers j=2jj,2jj+1): grp=lane>>3: matrix {j-lo, j-hi, j+1-lo, j+1-hi}
    uint32_t b_off[4];
    {
        const int grp = lane >> 3;              // 0..3
        const int bj = grp >> 1, bk = (grp & 1) * 8;
        #pragma unroll
        for (int jj = 0; jj < 4; jj++)
            b_off[jj] = (uint32_t)(((wn * 64 + (2 * jj + bj) * 8 + (lane & 7)) * 72 + bk) * 2);
    }

    float acc[4][8][4];
    #pragma unroll
    for (int i = 0; i < 4; i++)
        #pragma unroll
        for (int j = 0; j < 8; j++)
            #pragma unroll
            for (int r = 0; r < 4; r++) acc[i][j][r] = 0.f;

    const __half* Arow = A  + (size_t)m0 * lda;
    const __half* Brow = Bt + (size_t)n0 * K;

    auto load_stage = [&](int k0, int s) {   // k0 in halves
        const uint32_t base = sb + s * STG_B;
        #pragma unroll
        for (int c = 0; c < 8; c++) {        // A: 2048 16B chunks
            int chunk = tid + c * 256;
            int row = chunk >> 3, k16 = chunk & 7;
            cp_async16(base + row * 144 + k16 * 16,
                       Arow + (size_t)row * lda + k0 + k16 * 8);
        }
        #pragma unroll
        for (int c = 0; c < 4; c++) {        // B: 1024 16B chunks
            int chunk = tid + c * 256;
            int row = chunk >> 3, k16 = chunk & 7;
            cp_async16(base + A_BYTES2 + row * 144 + k16 * 16,
                       Brow + (size_t)row * K + k0 + k16 * 8);
        }
        cp_commit();
    };

    const int iters = K >> 6;
    load_stage(0, 0);
    load_stage(64, 1);

    for (int it = 0; it < iters; it++) {
        if (it + 1 < iters) cp_wait<1>();
        else                cp_wait<0>();
        __syncthreads();
        if (it + 2 < iters) load_stage((it + 2) * 64, (it + 2) % 3);

        const uint32_t sA = sb + (it % 3) * STG_B;
        const uint32_t sB = sA + A_BYTES2;

        #pragma unroll
        for (int ko = 0; ko < 4; ko++) {     // 4 x k16 per BK=64
            const uint32_t koff = ko * 32;   // 16 halves = 32 bytes
            uint32_t a[4][4], b[4][4];
            #pragma unroll
            for (int i = 0; i < 4; i++) ldm_x4(a[i], sA + a_off[i] + koff);
            #pragma unroll
            for (int jj = 0; jj < 4; jj++) ldm_x4(b[jj], sB + b_off[jj] + koff);
            #pragma unroll
            for (int i = 0; i < 4; i++)
                #pragma unroll
                for (int j = 0; j < 8; j++)
                    mma_f16(acc[i][j], a[i], &b[j >> 1][(j & 1) * 2]);
        }
    }

    // bias values: cols n0 + wn*64 + j*8 + 2t, +1
    const int g = lane >> 2;
    float bv[8][2];
    #pragma unroll
    for (int j = 0; j < 8; j++) {
        int col = n0 + wn * 64 + j * 8 + 2 * t;
        bv[j][0] = bias[col];
        bv[j][1] = bias[col + 1];
    }

    if (EPI == 0) {
        #pragma unroll
        for (int i = 0; i < 4; i++) {
            int r0 = m0 + wm * 64 + i * 16 + g;
            __half* c0 = C + (size_t)r0 * ldc + n0;
            __half* c1 = C + (size_t)(r0 + 8) * ldc + n0;
            #pragma unroll
            for (int j = 0; j < 8; j++) {
                int col = wn * 64 + j * 8 + 2 * t;
                *(__half2*)(c0 + col) = __floats2half2_rn(
                    fmaxf(acc[i][j][0] + bv[j][0], 0.f),
                    fmaxf(acc[i][j][1] + bv[j][1], 0.f));
                *(__half2*)(c1 + col) = __floats2half2_rn(
                    fmaxf(acc[i][j][2] + bv[j][0], 0.f),
                    fmaxf(acc[i][j][3] + bv[j][1], 0.f));
            }
        }
    } else {
        #pragma unroll
        for (int i = 0; i < 4; i++) {
            int r0 = m0 + wm * 64 + i * 16 + g;
            int q0 = batch[r0], q1 = batch[r0 + 8];
            float* o0 = out + (size_t)q0 * D_OUT;
            float* o1 = out + (size_t)q1 * D_OUT;
            #pragma unroll
            for (int j = 0; j < 8; j++) {
                int col = wn * 64 + j * 8 + 2 * t;   // n0 == 0 here
                atomicAdd(o0 + col,     acc[i][j][0] + bv[j][0]);
                atomicAdd(o0 + col + 1, acc[i][j][1] + bv[j][1]);
                atomicAdd(o1 + col,     acc[i][j][2] + bv[j][0]);
                atomicAdd(o1 + col + 1, acc[i][j][3] + bv[j][1]);
            }
        }
    }
}

// ---------------------------------------------------------------------------
// In-place row LayerNorm over D_H=1024 fp16; stats in fp32.
// 128 threads/row, 16B (8-half) loads per thread.
// ---------------------------------------------------------------------------
__global__ void __launch_bounds__(128)
ln_kernel(__half* __restrict__ X,
          const float* __restrict__ gamma,
          const float* __restrict__ beta)
{
    const int row = blockIdx.x;
    const int tid = threadIdx.x;
    __half* x = X + (size_t)row * D_H;

    uint4 u = *(const uint4*)(x + tid * 8);
    float2 p0 = __half22float2(*(__half2*)&u.x);
    float2 p1 = __half22float2(*(__half2*)&u.y);
    float2 p2 = __half22float2(*(__half2*)&u.z);
    float2 p3 = __half22float2(*(__half2*)&u.w);
    float s  = p0.x + p0.y + p1.x + p1.y + p2.x + p2.y + p3.x + p3.y;
    float sq = p0.x*p0.x + p0.y*p0.y + p1.x*p1.x + p1.y*p1.y
             + p2.x*p2.x + p2.y*p2.y + p3.x*p3.x + p3.y*p3.y;

    #pragma unroll
    for (int o = 16; o > 0; o >>= 1) {
        s  += __shfl_xor_sync(0xffffffffu, s, o);
        sq += __shfl_xor_sync(0xffffffffu, sq, o);
    }
    __shared__ float2 red[4];
    const int w = tid >> 5, l = tid & 31;
    if (l == 0) red[w] = make_float2(s, sq);
    __syncthreads();
    if (w == 0) {
        float2 p = (l < 4) ? red[l] : make_float2(0.f, 0.f);
        s = p.x; sq = p.y;
        #pragma unroll
        for (int o = 2; o > 0; o >>= 1) {
            s  += __shfl_xor_sync(0xffffffffu, s, o);
            sq += __shfl_xor_sync(0xffffffffu, sq, o);
        }
        if (l == 0) red[0] = make_float2(s, sq);
    }
    __syncthreads();

    const float mean = red[0].x * (1.0f / D_H);
    const float var  = red[0].y * (1.0f / D_H) - mean * mean;
    const float inv  = rsqrtf(var + LN_EPS);

    float4 g0 = *(const float4*)(gamma + tid * 8);
    float4 g1 = *(const float4*)(gamma + tid * 8 + 4);
    float4 b0 = *(const float4*)(beta  + tid * 8);
    float4 b1 = *(const float4*)(beta  + tid * 8 + 4);
    uint4 o;
    *(__half2*)&o.x = __floats2half2_rn((p0.x - mean) * inv * g0.x + b0.x,
                                        (p0.y - mean) * inv * g0.y + b0.y);
    *(__half2*)&o.y = __floats2half2_rn((p1.x - mean) * inv * g0.z + b0.z,
                                        (p1.y - mean) * inv * g0.w + b0.w);
    *(__half2*)&o.z = __floats2half2_rn((p2.x - mean) * inv * g1.x + b1.x,
                                        (p2.y - mean) * inv * g1.y + b1.y);
    *(__half2*)&o.w = __floats2half2_rn((p3.x - mean) * inv * g1.z + b1.z,
                                        (p3.y - mean) * inv * g1.w + b1.w);
    *(uint4*)(x + tid * 8) = o;
}

// ---------------------------------------------------------------------------
// Small helper kernels
// ---------------------------------------------------------------------------
__global__ void cvt_x_kernel(const float* __restrict__ src,
                             __half* __restrict__ dst, int n4)
{
    int i = blockIdx.x * blockDim.x + threadIdx.x;
    if (i < n4) {
        float4 v = ((const float4*)src)[i];
        uint2 o;
        *(__half2*)&o.x = __floats2half2_rn(v.x, v.y);
        *(__half2*)&o.y = __floats2half2_rn(v.z, v.w);
        ((uint2*)dst)[i] = o;
    }
}

// dst[n*K + k] = fp16(src[k*N + n]); grid (N/32, K/32), 256 threads
__global__ void wtrans_kernel(const float* __restrict__ src,
                              __half* __restrict__ dst, int K, int N)
{
    __shared__ float t[32][33];
    const int n0 = blockIdx.x * 32, k0 = blockIdx.y * 32;
    const int tx = threadIdx.x & 31, ty = threadIdx.x >> 5;
    #pragma unroll
    for (int r = ty; r < 32; r += 8)
        t[r][tx] = src[(size_t)(k0 + r) * N + n0 + tx];
    __syncthreads();
    #pragma unroll
    for (int r = ty; r < 32; r += 8)
        dst[(size_t)(n0 + r) * K + k0 + tx] = __float2half_rn(t[tx][r]);
}

__global__ void zero_kernel(float* __restrict__ out)
{
    int i = blockIdx.x * blockDim.x + threadIdx.x;
    if (i < NUM_GROUPS * D_OUT) out[i] = 0.f;
    if (i < NUM_GROUPS) g_counts[i] = 0.f;
}

__global__ void count_kernel(const int* __restrict__ batch)
{
    int i = blockIdx.x * blockDim.x + threadIdx.x;
    if (i < N_ROWS) atomicAdd(&g_counts[batch[i]], 1.0f);
}

__global__ void finalize_kernel(float* __restrict__ out)
{
    int i = blockIdx.x * blockDim.x + threadIdx.x;
    if (i < NUM_GROUPS * D_OUT) out[i] = out[i] / g_counts[i / D_OUT];
}

// ---------------------------------------------------------------------------
// kernel_launch
// Inputs: X, W1, b1, g1, be1, W2, b2, g2, be2, W3, b3, all_batch
// Layer-2 GEMM is the 6th launch (ncu -s 5 -c 1 captures it).
// ---------------------------------------------------------------------------
extern "C" void kernel_launch(void* const* d_in, const int* in_sizes, int n_in,
                              void* d_out, int out_size)
{
    const float* X   = (const float*)d_in[0];
    const float* W1  = (const float*)d_in[1];
    const float* b1  = (const float*)d_in[2];
    const float* g1  = (const float*)d_in[3];
    const float* be1 = (const float*)d_in[4];
    const float* W2  = (const float*)d_in[5];
    const float* b2  = (const float*)d_in[6];
    const float* g2  = (const float*)d_in[7];
    const float* be2 = (const float*)d_in[8];
    const float* W3  = (const float*)d_in[9];
    const float* b3  = (const float*)d_in[10];
    const int*   batch = (const int*)d_in[11];
    float* outp = (float*)d_out;

    __half *h1, *h2, *xh, *w1t, *w2t, *w3t;
    cudaGetSymbolAddress((void**)&h1,  g_h1);
    cudaGetSymbolAddress((void**)&h2,  g_h2);
    cudaGetSymbolAddress((void**)&xh,  g_xh);
    cudaGetSymbolAddress((void**)&w1t, g_w1t);
    cudaGetSymbolAddress((void**)&w2t, g_w2t);
    cudaGetSymbolAddress((void**)&w3t, g_w3t);

    cudaFuncSetAttribute(h_gemm<0>,
        cudaFuncAttributeMaxDynamicSharedMemorySize, GEMM_SMEM);
    cudaFuncSetAttribute(h_gemm<1>,
        cudaFuncAttributeMaxDynamicSharedMemorySize, GEMM_SMEM);

    // 1: X -> fp16
    cvt_x_kernel<<<(N_ROWS * D_IN / 4 + 255) / 256, 256>>>(X, xh, N_ROWS * D_IN / 4);
    // 2-3: W1,W2 transpose -> fp16 [N][K]
    wtrans_kernel<<<dim3(D_H / 32, D_IN / 32), 256>>>(W1, w1t, D_IN, D_H);
    wtrans_kernel<<<dim3(D_H / 32, D_H  / 32), 256>>>(W2, w2t, D_H,  D_H);

    // 4: layer 1  h1 = relu(X @ W1 + b1)
    h_gemm<0><<<dim3(D_H / 128, N_ROWS / 256), 256, GEMM_SMEM>>>(
        xh, w1t, b1, h1, D_IN, D_IN, D_H, nullptr, nullptr);
    // 5: LN1
    ln_kernel<<<N_ROWS, 128>>>(h1, g1, be1);

    // 6: layer 2  h2 = relu(h1 @ W2 + b2)   [ncu capture target]
    h_gemm<0><<<dim3(D_H / 128, N_ROWS / 256), 256, GEMM_SMEM>>>(
        h1, w2t, b2, h2, D_H, D_H, D_H, nullptr, nullptr);
    // 7: LN2
    ln_kernel<<<N_ROWS, 128>>>(h2, g2, be2);

    // 8: W3 transpose; 9: zero out+counts; 10: per-group counts
    wtrans_kernel<<<dim3(D_OUT / 32, D_H / 32), 256>>>(W3, w3t, D_H, D_OUT);
    zero_kernel<<<(NUM_GROUPS * D_OUT + 255) / 256, 256>>>(outp);
    count_kernel<<<(N_ROWS + 255) / 256, 256>>>(batch);

    // 11: layer 3 + segment-sum atomics
    h_gemm<1><<<dim3(1, N_ROWS / 256), 256, GEMM_SMEM>>>(
        h2, w3t, b3, nullptr, D_H, D_H, D_OUT, batch, outp);

    // 12: mean = sum / count
    finalize_kernel<<<(NUM_GROUPS * D_OUT + 255) / 256, 256>>>(outp);
}